// round 6
// baseline (speedup 1.0000x reference)
#include <cuda_runtime.h>

#define NLAY 5
#define MIX  5
#define MF   50

typedef unsigned long long u64;

__device__ double g_p1[1024];
__device__ double g_p2[1024];
__device__ unsigned int g_cnt = 0;

// ---- f32x2 packed helpers (sm_100+: FFMA2/FMUL2/FADD2) ----
__device__ __forceinline__ u64 PK(float lo, float hi) {
    u64 r; asm("mov.b64 %0,{%1,%2};" : "=l"(r) : "f"(lo), "f"(hi)); return r;
}
__device__ __forceinline__ void UPK(u64 v, float& lo, float& hi) {
    asm("mov.b64 {%0,%1},%2;" : "=f"(lo), "=f"(hi) : "l"(v));
}
__device__ __forceinline__ u64 SP(float x) { return PK(x, x); }
__device__ __forceinline__ u64 F2(u64 a, u64 b, u64 c) {
    u64 r; asm("fma.rn.f32x2 %0,%1,%2,%3;" : "=l"(r) : "l"(a), "l"(b), "l"(c)); return r;
}
__device__ __forceinline__ u64 M2(u64 a, u64 b) {
    u64 r; asm("mul.rn.f32x2 %0,%1,%2;" : "=l"(r) : "l"(a), "l"(b)); return r;
}
__device__ __forceinline__ u64 A2(u64 a, u64 b) {
    u64 r; asm("add.rn.f32x2 %0,%1,%2;" : "=l"(r) : "l"(a), "l"(b)); return r;
}
__device__ __forceinline__ u64 N2(u64 a) { return a ^ 0x8000000080000000ULL; }

__device__ __forceinline__ float sigmoidf_(float v) {
    return __fdividef(1.f, 1.f + __expf(-v));
}
__device__ __forceinline__ float softplusf_(float v) {
    return fmaxf(v, 0.f) + __logf(1.f + __expf(-fabsf(v)));
}
// Abramowitz-Stegun 26.2.17 normal CDF, |abs err| < 7.5e-8
__device__ __forceinline__ float ndtr_(float x) {
    float ax = fabsf(x);
    float t = __fdividef(1.f, fmaf(0.2316419f, ax, 1.f));
    float poly = t * fmaf(t, fmaf(t, fmaf(t, fmaf(t, 1.330274429f, -1.821255978f),
                         1.781477937f), -0.356563782f), 0.319381530f);
    float c = 0.39894228040f * __expf(-0.5f * ax * ax) * poly;
    return (x >= 0.f) ? 1.f - c : c;
}

__global__ __launch_bounds__(256) void bnn_all(
    const float* __restrict__ x, const float* __restrict__ s,
    const float* __restrict__ ucat, const float* __restrict__ utr,
    float* __restrict__ out, int B)
{
    // ---- per-block frequency tables ----
    __shared__ float s_cf[MF], s_lmw[MF];
    if (threadIdx.x < MF) {
        int i = threadIdx.x;
        s_cf[i]  = 1.9869176531e-4f * exp2f(0.16948612698f * (float)i);
        s_lmw[i] = -7.1025448154f + 0.1020408163f * (float)i;
    }
    __syncthreads();

    int t    = blockIdx.x * blockDim.x + threadIdx.x;
    int b    = t >> 1;       // element index: 2 threads per element
    int half = t & 1;        // lane-pair half
    float ll_sum = 0.f;
    float lq = 0.f;
    if (b < B) {
        const float* sb = s + (size_t)b * 55;
        const float* xb = x + (size_t)b * 105;

        // ---- mixture weights (both halves, cheap) ----
        float sq[MIX]; float sumsq = 0.f;
        #pragma unroll
        for (int m = 0; m < MIX; m++) { float v = sb[m*11 + 10]; sq[m] = v*v; sumsq += sq[m]; }
        float rinv = __fdividef(1.f, sumsq);

        // ---- categorical selection ----
        float u = ucat[b];
        float cum = 0.f; int cnt = 0;
        #pragma unroll
        for (int m = 0; m < MIX; m++) { cum += sq[m] * rinv; cnt += (u > cum) ? 1 : 0; }
        int comp = min(cnt, MIX - 1);

        // ---- truncated-normal sampling: lane0 does l=0..2, lane1 does l=3..4 ----
        float q[NLAY];
        const float* sc = sb + comp * 11;
        #pragma unroll
        for (int i = 0; i < 3; i++) {
            int l = i + 3 * half;
            if (l < NLAY) {
                float lc = 4.f * sigmoidf_(sc[l]);
                float sg = softplusf_(sc[5 + l]);
                float rs = __fdividef(1.f, sg);
                float aa = (0.1f - lc) * rs;
                float bb = (3.9f - lc) * rs;
                float Fa = ndtr_(aa);
                float Fb = ndtr_(bb);
                float p  = Fa + utr[(size_t)b * NLAY + l] * (Fb - Fa);
                p = fminf(fmaxf(p, 0.f), 1.f);
                float z = normcdfinvf(p);
                q[l] = fminf(fmaxf(fmaf(sg, z, lc), 0.1f), 3.9f);
            }
        }
        // exchange q with partner lane
        #pragma unroll
        for (int l = 0; l < NLAY; l++) {
            float o = __shfl_xor_sync(0xffffffffu, q[l], 1);
            if ((l >= 3) != (half == 1)) q[l] = o;
        }

        // ---- physics precompute (both halves) ----
        float sr[NLAY], tq[NLAY - 1];
        #pragma unroll
        for (int l = 0; l < NLAY; l++) sr[l] = exp2f(q[l] * 1.66096404744368f);
        #pragma unroll
        for (int j = 0; j < NLAY - 1; j++) tq[j] = 2.f * xb[j] * __fdividef(1.f, sr[j]);

        // ---- packed constants ----
        const u64 C130 = SP(0.033333335f), Cm16 = SP(-0.16666667f);
        const u64 C13  = SP(0.33333334f),  Cm13 = SP(-0.33333334f);
        const u64 ONE2 = SP(1.0f);
        const u64 A1  = SP(0.9999993329f),  A3  = SP(-0.3332985605f);
        const u64 A5  = SP(0.1994653599f),  A7  = SP(-0.1390853351f);
        const u64 A9  = SP(0.0964200441f),  A11 = SP(-0.0559098861f);
        const u64 A13 = SP(0.0218612288f),  A15 = SP(-0.0040540580f);
        const u64 C555 = SP(-555.555556f), CLN2 = SP(-0.69314718f);
        const u64 CC = SP(2.58761937f), CL102 = SP(0.30102999566f);

        u64 acc2 = 0ull;

        // ---- frequency loop: lane0 takes pairs p%4==0, lane1 p%4==2 ----
        #pragma unroll 1
        for (int it = 0; it < 13; it++) {
            int p = 4 * it + 2 * half;
            if (p < MF) {
                u64 cf2 = PK(s_cf[p], s_cf[p + 1]);
                u64 NRv = M2(cf2, SP(sr[NLAY - 1]));   // Z_bottom as ratio N/D
                u64 NCv = NRv;
                u64 DRv = ONE2, DCv = 0ull;
                #pragma unroll
                for (int j = NLAY - 2; j >= 0; j--) {
                    u64 wj = M2(cf2, SP(sr[j]));
                    u64 tt = M2(cf2, SP(tq[j]));
                    u64 t2 = M2(tt, tt);
                    u64 nt = N2(tt);
                    u64 pr = F2(tt, C130, Cm16);  pr = F2(pr, tt, C13);
                    u64 t3 = M2(tt, t2);
                    u64 omt = A2(ONE2, nt);
                    u64 ejR = F2(pr, t3, omt);
                    u64 pc = F2(t2, C130, Cm13); pc = F2(pc, tt, ONE2);
                    u64 ejC = F2(pc, t2, nt);
                    u64 wdr = M2(wj, A2(DRv, N2(DCv)));
                    u64 wdc = M2(wj, A2(DRv, DCv));
                    u64 PRv = A2(wdr, NRv), PCv = A2(wdc, NCv);
                    u64 MRv = A2(wdr, N2(NRv)), MCv = A2(wdc, N2(NCv));
                    u64 eMR = F2(ejR, MRv, N2(M2(ejC, MCv)));
                    u64 eMC = F2(ejR, MCv, M2(ejC, MRv));
                    u64 ARv = A2(PRv, N2(eMR)), ACv = A2(PCv, N2(eMC));
                    DRv = A2(PRv, eMR); DCv = A2(PCv, eMC);
                    NRv = M2(wj, A2(ARv, N2(ACv)));
                    NCv = M2(wj, A2(ARv, ACv));
                }
                u64 n2v = F2(NRv, NRv, M2(NCv, NCv));
                u64 d2v = F2(DRv, DRv, M2(DCv, DCv));
                u64 ZRv = F2(NCv, DCv, M2(NRv, DRv));
                u64 ZCv = F2(NCv, DRv, N2(M2(NRv, DCv)));
                float n2a, n2b, d2a, d2b, zra, zrb, zca, zcb;
                UPK(n2v, n2a, n2b); UPK(d2v, d2a, d2b);
                UPK(ZRv, zra, zrb); UPK(ZCv, zca, zcb);

                u64 lgv = PK(__log2f(n2a) - __log2f(d2a), __log2f(n2b) - __log2f(d2b));
                u64 aResV = F2(CL102, lgv, PK(-s_lmw[p], -s_lmw[p + 1]));
                float aA, aB; UPK(aResV, aA, aB);

                float r0 = __fdividef(fminf(zca, zra), fmaxf(zca, zra));
                float r1 = __fdividef(fminf(zcb, zrb), fmaxf(zcb, zrb));
                u64 rv = PK(r0, r1);
                u64 sv = M2(rv, rv);
                u64 pp = F2(sv, A15, A13); pp = F2(pp, sv, A11);
                pp = F2(pp, sv, A9);       pp = F2(pp, sv, A7);
                pp = F2(pp, sv, A5);       pp = F2(pp, sv, A3);
                pp = F2(pp, sv, A1);
                u64 av = M2(pp, rv);
                float at0, at1; UPK(av, at0, at1);
                float ph0 = (zca > zra) ? (1.57079632679f - at0) : at0;
                float ph1 = (zcb > zrb) ? (1.57079632679f - at1) : at1;

                float ra0 = __fdividef(aA - xb[NLAY + p],     aA);
                float ra1 = __fdividef(aB - xb[NLAY + p + 1], aB);
                u64 rAv = PK(ra0, ra1);
                u64 lgA = PK(__log2f(fabsf(aA)), __log2f(fabsf(aB)));
                acc2 = A2(acc2, F2(C555, M2(rAv, rAv), F2(CLN2, lgA, CC)));

                float rp0 = __fdividef(ph0 - xb[NLAY + MF + p],     ph0);
                float rp1 = __fdividef(ph1 - xb[NLAY + MF + p + 1], ph1);
                u64 rPv = PK(rp0, rp1);
                u64 lgP = PK(__log2f(ph0), __log2f(ph1));
                acc2 = A2(acc2, F2(C555, M2(rPv, rPv), F2(CLN2, lgP, CC)));
            }
        }
        { float la, lb_; UPK(acc2, la, lb_); ll_sum = la + lb_; }

        // ---- term_q: lane0 comps {0,2,4}, lane1 {1,3}; online LSE + exchange ----
        float mx = -1e30f, se = 0.f;
        #pragma unroll
        for (int i = 0; i < 3; i++) {
            int m = 2 * i + half;
            if (m < MIX) {
                float acc = __logf(sq[m] * rinv);
                const float* sm = sb + m * 11;
                #pragma unroll
                for (int l = 0; l < NLAY; l++) {
                    float lc = 4.f * sigmoidf_(sm[l]);
                    float sg = softplusf_(sm[5 + l]);
                    float rs = __fdividef(1.f, sg);
                    float a_ = (0.f - lc) * rs;
                    float b_ = (4.f - lc) * rs;
                    float dF = ndtr_(b_) - ndtr_(a_);
                    float zc = (q[l] - lc) * rs;
                    acc += fmaf(-0.5f, zc * zc, -0.91893853f) - __logf(sg) - __logf(dF);
                }
                float nm = fmaxf(mx, acc);
                se = se * __expf(mx - nm) + __expf(acc - nm);
                mx = nm;
            }
        }
        float mxo = __shfl_xor_sync(0xffffffffu, mx, 1);
        float seo = __shfl_xor_sync(0xffffffffu, se, 1);
        float M  = fmaxf(mx, mxo);
        float sT = se * __expf(mx - M) + seo * __expf(mxo - M);
        lq = (half == 0) ? (M + __logf(sT)) : 0.f;
    }

    // ---- block reduction (double) ----
    double v1 = (double)ll_sum, v2 = (double)lq;
    #pragma unroll
    for (int o = 16; o > 0; o >>= 1) {
        v1 += __shfl_down_sync(0xffffffffu, v1, o);
        v2 += __shfl_down_sync(0xffffffffu, v2, o);
    }
    __shared__ double sh1[8], sh2[8];
    __shared__ bool amLast;
    int lane = threadIdx.x & 31, wid = threadIdx.x >> 5;
    if (lane == 0) { sh1[wid] = v1; sh2[wid] = v2; }
    __syncthreads();
    if (wid == 0) {
        int nw = blockDim.x >> 5;
        double a = (lane < nw) ? sh1[lane] : 0.0;
        double c = (lane < nw) ? sh2[lane] : 0.0;
        #pragma unroll
        for (int o = 4; o > 0; o >>= 1) {
            a += __shfl_down_sync(0xffffffffu, a, o);
            c += __shfl_down_sync(0xffffffffu, c, o);
        }
        if (lane == 0) {
            g_p1[blockIdx.x] = a;
            g_p2[blockIdx.x] = c;
            __threadfence();
            unsigned int tt = atomicAdd(&g_cnt, 1u);
            amLast = (tt == gridDim.x - 1);
        }
    }
    __syncthreads();

    // ---- last block: final reduction + output ----
    if (amLast) {
        __threadfence();
        double s1 = 0.0, s2 = 0.0;
        for (int i = threadIdx.x; i < (int)gridDim.x; i += blockDim.x) {
            s1 += __ldcg(&g_p1[i]);
            s2 += __ldcg(&g_p2[i]);
        }
        #pragma unroll
        for (int o = 16; o > 0; o >>= 1) {
            s1 += __shfl_down_sync(0xffffffffu, s1, o);
            s2 += __shfl_down_sync(0xffffffffu, s2, o);
        }
        __syncthreads();
        if (lane == 0) { sh1[wid] = s1; sh2[wid] = s2; }
        __syncthreads();
        if (wid == 0) {
            int nw = blockDim.x >> 5;
            double a = (lane < nw) ? sh1[lane] : 0.0;
            double c = (lane < nw) ? sh2[lane] : 0.0;
            #pragma unroll
            for (int o = 4; o > 0; o >>= 1) {
                a += __shfl_down_sync(0xffffffffu, a, o);
                c += __shfl_down_sync(0xffffffffu, c, o);
            }
            if (lane == 0) {
                double term_lik = -a / ((double)B * (double)(2 * MF));
                double term_q   =  c / (double)B;
                out[0] = (float)(term_lik + term_q + 1.3862943611198906); // + log(4)
                g_cnt = 0;
            }
        }
    }
}

extern "C" void kernel_launch(void* const* d_in, const int* in_sizes, int n_in,
                              void* d_out, int out_size)
{
    const float* x    = (const float*)d_in[0];
    const float* s    = (const float*)d_in[1];
    const float* ucat = (const float*)d_in[2];
    const float* utr  = (const float*)d_in[3];
    int B = in_sizes[0] / 105;

    int threads = 256;
    int blocks = (2 * B + threads - 1) / threads;   // 1024 for B=131072
    bnn_all<<<blocks, threads>>>(x, s, ucat, utr, (float*)d_out, B);
}

// round 7
// speedup vs baseline: 1.1703x; 1.1703x over previous
#include <cuda_runtime.h>

#define NLAY 5
#define MIX  5
#define MF   50

typedef unsigned long long u64;

__device__ double g_p1[1024];
__device__ double g_p2[1024];
__device__ unsigned int g_cnt = 0;

// ---- f32x2 packed helpers (sm_100+: FFMA2/FMUL2/FADD2) ----
__device__ __forceinline__ u64 PK(float lo, float hi) {
    u64 r; asm("mov.b64 %0,{%1,%2};" : "=l"(r) : "f"(lo), "f"(hi)); return r;
}
__device__ __forceinline__ void UPK(u64 v, float& lo, float& hi) {
    asm("mov.b64 {%0,%1},%2;" : "=f"(lo), "=f"(hi) : "l"(v));
}
__device__ __forceinline__ u64 SP(float x) { return PK(x, x); }
__device__ __forceinline__ u64 F2(u64 a, u64 b, u64 c) {
    u64 r; asm("fma.rn.f32x2 %0,%1,%2,%3;" : "=l"(r) : "l"(a), "l"(b), "l"(c)); return r;
}
__device__ __forceinline__ u64 M2(u64 a, u64 b) {
    u64 r; asm("mul.rn.f32x2 %0,%1,%2;" : "=l"(r) : "l"(a), "l"(b)); return r;
}
__device__ __forceinline__ u64 A2(u64 a, u64 b) {
    u64 r; asm("add.rn.f32x2 %0,%1,%2;" : "=l"(r) : "l"(a), "l"(b)); return r;
}

__device__ __forceinline__ float sigmoidf_(float v) {
    return __fdividef(1.f, 1.f + __expf(-v));
}
__device__ __forceinline__ float softplusf_(float v) {
    return fmaxf(v, 0.f) + __logf(1.f + __expf(-fabsf(v)));
}
// Abramowitz-Stegun 26.2.17 normal CDF, |abs err| < 7.5e-8
__device__ __forceinline__ float ndtr_(float x) {
    float ax = fabsf(x);
    float t = __fdividef(1.f, fmaf(0.2316419f, ax, 1.f));
    float poly = t * fmaf(t, fmaf(t, fmaf(t, fmaf(t, 1.330274429f, -1.821255978f),
                         1.781477937f), -0.356563782f), 0.319381530f);
    float c = 0.39894228040f * __expf(-0.5f * ax * ax) * poly;
    return (x >= 0.f) ? 1.f - c : c;
}

__global__ __launch_bounds__(128, 8) void bnn_all(
    const float* __restrict__ x, const float* __restrict__ s,
    const float* __restrict__ ucat, const float* __restrict__ utr,
    float* __restrict__ out, int B)
{
    // ---- per-block frequency tables ----
    // s_cf  = sqrt(w*MU/2) = 2pi*10^-4.5 * 2^(log2(10)*5i/98)
    // s_nlm = 0.30103 - log10(MU*w)  (the +0.30103 absorbs the factor 2 in |Z|^2 = 2|N|^2/|D|^2)
    __shared__ float s_cf[MF], s_nlm[MF];
    if (threadIdx.x < MF) {
        int i = threadIdx.x;
        s_cf[i]  = 1.9869176531e-4f * exp2f(0.16948612698f * (float)i);
        s_nlm[i] = 7.4035748111f - 0.1020408163f * (float)i;
    }
    __syncthreads();

    int b = blockIdx.x * blockDim.x + threadIdx.x;
    float ll_sum = 0.f;
    float lq = 0.f;
    if (b < B) {
        const float* sb = s + (size_t)b * 55;
        const float* xb = x + (size_t)b * 105;

        // ---- mixture weights ----
        float sq[MIX]; float sumsq = 0.f;
        #pragma unroll
        for (int m = 0; m < MIX; m++) { float v = sb[m*11 + 10]; sq[m] = v*v; sumsq += sq[m]; }
        float rinv = __fdividef(1.f, sumsq);

        // ---- categorical selection ----
        float u = ucat[b];
        float cum = 0.f; int cnt = 0;
        #pragma unroll
        for (int m = 0; m < MIX; m++) { cum += sq[m] * rinv; cnt += (u > cum) ? 1 : 0; }
        int comp = min(cnt, MIX - 1);

        // ---- truncated-normal sampling ----
        float q[NLAY];
        const float* sc = sb + comp * 11;
        #pragma unroll
        for (int l = 0; l < NLAY; l++) {
            float lc = 4.f * sigmoidf_(sc[l]);
            float sg = softplusf_(sc[5 + l]);
            float rs = __fdividef(1.f, sg);
            float aa = (0.1f - lc) * rs;
            float bb = (3.9f - lc) * rs;
            float Fa = ndtr_(aa);
            float Fb = ndtr_(bb);
            float p  = Fa + utr[(size_t)b * NLAY + l] * (Fb - Fa);
            p = fminf(fmaxf(p, 0.f), 1.f);
            float z = normcdfinvf(p);
            q[l] = fminf(fmaxf(fmaf(sg, z, lc), 0.1f), 3.9f);
        }

        // ---- physics precompute ----
        float sr[NLAY], tq[NLAY - 1];
        #pragma unroll
        for (int l = 0; l < NLAY; l++) sr[l] = exp2f(q[l] * 1.66096404744368f);
        #pragma unroll
        for (int j = 0; j < NLAY - 1; j++) tq[j] = 2.f * xb[j] * __fdividef(1.f, sr[j]);

        // ---- packed constants ----
        const u64 C130 = SP(0.033333335f), Cm16 = SP(-0.16666667f);
        const u64 C13  = SP(0.33333334f),  Cm13 = SP(-0.33333334f);
        const u64 ONE2 = SP(1.0f), Cm1 = SP(-1.0f);
        const u64 A1  = SP(0.9999993329f),  A3  = SP(-0.3332985605f);
        const u64 A5  = SP(0.1994653599f),  A7  = SP(-0.1390853351f);
        const u64 A9  = SP(0.0964200441f),  A11 = SP(-0.0559098861f);
        const u64 A13 = SP(0.0218612288f),  A15 = SP(-0.0040540580f);
        const u64 C555 = SP(-555.555556f), CLN2 = SP(-0.69314718f);
        const u64 CC = SP(2.58761937f), CL102 = SP(0.30102999566f);
        const u64 PI4 = SP(0.78539816340f);

        u64 acc2 = 0ull;

        // ---- frequency loop: 2 freqs/iter via f32x2, (1+i)-factored recursion ----
        // Track Ntil = N/(1+i): all layer transfer matrices become real-w forms.
        // Z = (1+i)*Ntil/D  =>  |Z|^2 = 2|Ntil|^2/|D|^2,  arg Z = pi/4 + arg(Ntil*conj(D))
        #pragma unroll 1
        for (int p = 0; p < MF; p += 2) {
            u64 cf2 = PK(s_cf[p], s_cf[p + 1]);
            u64 N0 = M2(cf2, SP(sr[NLAY - 1]));   // Ntil_bottom = cf*sr4 (real)

            // --- peeled layer j=3 (D=1, Ntil real) ---
            u64 NRv, NCv, DRv, DCv;
            {
                u64 wj = M2(cf2, SP(sr[3]));
                u64 tt = M2(cf2, SP(tq[3]));
                u64 t2 = M2(tt, tt);
                u64 pr = F2(tt, C130, Cm16);  pr = F2(pr, tt, C13);
                u64 t3 = M2(tt, t2);
                u64 omt = F2(tt, Cm1, ONE2);
                u64 ejR = F2(pr, t3, omt);
                u64 pc = F2(t2, C130, Cm13);  pc = F2(pc, tt, ONE2);
                u64 nt = M2(tt, Cm1);
                u64 ejC = F2(pc, t2, nt);
                u64 PR = A2(wj, N0);
                u64 MR = F2(N0, Cm1, wj);
                u64 eMR = M2(ejR, MR);
                u64 eMC = M2(ejC, MR);
                NRv = M2(wj, F2(eMR, Cm1, PR));
                NCv = M2(wj, M2(eMC, Cm1));
                DRv = A2(PR, eMR);
                DCv = eMC;
            }
            // --- layers j=2,1,0 ---
            #pragma unroll
            for (int j = 2; j >= 0; j--) {
                u64 wj = M2(cf2, SP(sr[j]));
                u64 tt = M2(cf2, SP(tq[j]));
                u64 t2 = M2(tt, tt);
                u64 pr = F2(tt, C130, Cm16);  pr = F2(pr, tt, C13);
                u64 t3 = M2(tt, t2);
                u64 omt = F2(tt, Cm1, ONE2);
                u64 ejR = F2(pr, t3, omt);
                u64 pc = F2(t2, C130, Cm13);  pc = F2(pc, tt, ONE2);
                u64 nt = M2(tt, Cm1);
                u64 ejC = F2(pc, t2, nt);
                u64 wdr = M2(wj, DRv), wdc = M2(wj, DCv);
                u64 PR = A2(wdr, NRv), PC = A2(wdc, NCv);
                u64 MR = F2(NRv, Cm1, wdr), MC = F2(NCv, Cm1, wdc);
                u64 nEjC = M2(ejC, Cm1);
                u64 eMR = F2(nEjC, MC, M2(ejR, MR));
                u64 eMC = F2(ejC, MR, M2(ejR, MC));
                NRv = M2(wj, F2(eMR, Cm1, PR));
                NCv = M2(wj, F2(eMC, Cm1, PC));
                DRv = A2(PR, eMR);
                DCv = A2(PC, eMC);
            }
            u64 n2v = F2(NRv, NRv, M2(NCv, NCv));
            u64 d2v = F2(DRv, DRv, M2(DCv, DCv));
            // ntil * conj(D)
            u64 nrv = F2(NRv, DRv, M2(NCv, DCv));
            u64 ncv = F2(NCv, DRv, M2(M2(NRv, DCv), Cm1));
            float n2a, n2b, d2a, d2b, ra_, rb_, ca_, cb_;
            UPK(n2v, n2a, n2b); UPK(d2v, d2a, d2b);
            UPK(nrv, ra_, rb_); UPK(ncv, ca_, cb_);

            // aRes = 0.30103*(log2 n2 - log2 d2) + (0.30103 - lmw)
            u64 lgv = PK(__log2f(n2a) - __log2f(d2a), __log2f(n2b) - __log2f(d2b));
            u64 aResV = F2(CL102, lgv, PK(s_nlm[p], s_nlm[p + 1]));
            float aA, aB; UPK(aResV, aA, aB);

            // phase = pi/4 + atan(nc/nr), |nc/nr| < 1 guaranteed
            float r0 = __fdividef(ca_, ra_);
            float r1 = __fdividef(cb_, rb_);
            u64 rv = PK(r0, r1);
            u64 sv = M2(rv, rv);
            u64 pp = F2(sv, A15, A13); pp = F2(pp, sv, A11);
            pp = F2(pp, sv, A9);       pp = F2(pp, sv, A7);
            pp = F2(pp, sv, A5);       pp = F2(pp, sv, A3);
            pp = F2(pp, sv, A1);
            u64 phv = F2(pp, rv, PI4);
            float ph0, ph1; UPK(phv, ph0, ph1);

            // log-likelihood (amplitude + phase), packed accumulate
            float ra0 = __fdividef(aA - xb[NLAY + p],     aA);
            float ra1 = __fdividef(aB - xb[NLAY + p + 1], aB);
            u64 rAv = PK(ra0, ra1);
            u64 lgA = PK(__log2f(fabsf(aA)), __log2f(fabsf(aB)));
            acc2 = A2(acc2, F2(C555, M2(rAv, rAv), F2(CLN2, lgA, CC)));

            float rp0 = __fdividef(ph0 - xb[NLAY + MF + p],     ph0);
            float rp1 = __fdividef(ph1 - xb[NLAY + MF + p + 1], ph1);
            u64 rPv = PK(rp0, rp1);
            u64 lgP = PK(__log2f(ph0), __log2f(ph1));
            acc2 = A2(acc2, F2(C555, M2(rPv, rPv), F2(CLN2, lgP, CC)));
        }
        { float la, lb_; UPK(acc2, la, lb_); ll_sum = la + lb_; }

        // ---- term_q: log q(samples) under full truncated mixture ----
        float clp[MIX];
        #pragma unroll
        for (int m = 0; m < MIX; m++) {
            float acc = __logf(sq[m] * rinv);
            const float* sm = sb + m * 11;
            #pragma unroll
            for (int l = 0; l < NLAY; l++) {
                float lc = 4.f * sigmoidf_(sm[l]);
                float sg = softplusf_(sm[5 + l]);
                float rs = __fdividef(1.f, sg);
                float a_ = (0.f - lc) * rs;
                float b_ = (4.f - lc) * rs;
                float dF = ndtr_(b_) - ndtr_(a_);
                float zc = (q[l] - lc) * rs;
                acc += fmaf(-0.5f, zc * zc, -0.91893853f) - __logf(sg) - __logf(dF);
            }
            clp[m] = acc;
        }
        float mx = clp[0];
        #pragma unroll
        for (int m = 1; m < MIX; m++) mx = fmaxf(mx, clp[m]);
        float se = 0.f;
        #pragma unroll
        for (int m = 0; m < MIX; m++) se += __expf(clp[m] - mx);
        lq = mx + __logf(se);
    }

    // ---- block reduction (double), 128 threads = 4 warps ----
    double v1 = (double)ll_sum, v2 = (double)lq;
    #pragma unroll
    for (int o = 16; o > 0; o >>= 1) {
        v1 += __shfl_down_sync(0xffffffffu, v1, o);
        v2 += __shfl_down_sync(0xffffffffu, v2, o);
    }
    __shared__ double sh1[4], sh2[4];
    __shared__ bool amLast;
    int lane = threadIdx.x & 31, wid = threadIdx.x >> 5;
    if (lane == 0) { sh1[wid] = v1; sh2[wid] = v2; }
    __syncthreads();
    if (wid == 0) {
        double a = (lane < 4) ? sh1[lane] : 0.0;
        double c = (lane < 4) ? sh2[lane] : 0.0;
        #pragma unroll
        for (int o = 2; o > 0; o >>= 1) {
            a += __shfl_down_sync(0xffffffffu, a, o);
            c += __shfl_down_sync(0xffffffffu, c, o);
        }
        if (lane == 0) {
            g_p1[blockIdx.x] = a;
            g_p2[blockIdx.x] = c;
            __threadfence();
            unsigned int t = atomicAdd(&g_cnt, 1u);
            amLast = (t == gridDim.x - 1);
        }
    }
    __syncthreads();

    // ---- last block: final reduction + output ----
    if (amLast) {
        __threadfence();
        double s1 = 0.0, s2 = 0.0;
        for (int i = threadIdx.x; i < (int)gridDim.x; i += blockDim.x) {
            s1 += __ldcg(&g_p1[i]);
            s2 += __ldcg(&g_p2[i]);
        }
        #pragma unroll
        for (int o = 16; o > 0; o >>= 1) {
            s1 += __shfl_down_sync(0xffffffffu, s1, o);
            s2 += __shfl_down_sync(0xffffffffu, s2, o);
        }
        __syncthreads();
        if (lane == 0) { sh1[wid] = s1; sh2[wid] = s2; }
        __syncthreads();
        if (wid == 0) {
            double a = (lane < 4) ? sh1[lane] : 0.0;
            double c = (lane < 4) ? sh2[lane] : 0.0;
            #pragma unroll
            for (int o = 2; o > 0; o >>= 1) {
                a += __shfl_down_sync(0xffffffffu, a, o);
                c += __shfl_down_sync(0xffffffffu, c, o);
            }
            if (lane == 0) {
                double term_lik = -a / ((double)B * (double)(2 * MF));
                double term_q   =  c / (double)B;
                out[0] = (float)(term_lik + term_q + 1.3862943611198906); // + log(4)
                g_cnt = 0;
            }
        }
    }
}

extern "C" void kernel_launch(void* const* d_in, const int* in_sizes, int n_in,
                              void* d_out, int out_size)
{
    const float* x    = (const float*)d_in[0];
    const float* s    = (const float*)d_in[1];
    const float* ucat = (const float*)d_in[2];
    const float* utr  = (const float*)d_in[3];
    int B = in_sizes[0] / 105;

    int threads = 128;
    int blocks = (B + threads - 1) / threads;   // 1024 for B=131072
    bnn_all<<<blocks, threads>>>(x, s, ucat, utr, (float*)d_out, B);
}